// round 7
// baseline (speedup 1.0000x reference)
#include <cuda_runtime.h>

#define HW    16384
#define CCH   256
#define CHW   4194304   // 256*16384
#define NIMG  8

// g_acc[q*2048 + n*256 + c], q: 0 chS, 1 chT, 2 SS2, 3 SD, 4 FG, 5 BG, 6 CXS, 7 CXT
__device__ float  g_acc[16384];
__device__ float4 g_wpx[NIMG * HW];   // per-pixel weights: eT*mf, eT*bgi, ecS, ecT
__device__ float  g_eS[NIMG * HW];
__device__ float  g_eT[NIMG * HW];
__device__ float4 g_zpart[512];       // per passA block: zfeaS, zfeaT, zcmS, zcmT
__device__ float  g_bgpart[512];      // per passA block: bg pixel count
__device__ float  g_spart[NIMG];      // per-image spatial L1 (from passB cg==0)

__device__ __forceinline__ float warpSum(float v) {
#pragma unroll
    for (int o = 16; o; o >>= 1) v += __shfl_xor_sync(0xffffffffu, v, o);
    return v;
}

// ---------------- pass A: mask + per-pixel channel sums ----------------
// grid 512 = 8 images x 64 blocks of 256 pixels; thread t <-> pixel.
// Warp loads 128B contiguous per channel; loops 256 channels (stride 64KB).
__global__ __launch_bounds__(256) void passA_kernel(
    const float* __restrict__ S, const float* __restrict__ T,
    const float* __restrict__ gt,
    const float* __restrict__ w_ms, const float* __restrict__ w_mt) {
    __shared__ float bx[100];          // wmin,wmax,hmin,hmax,area x20
    __shared__ float wms[256], wmt[256];
    __shared__ float rb[5][8];
    int t = threadIdx.x, bid = blockIdx.x;
    int n = bid >> 6;
    int pix = (bid & 63) * 256 + t;    // pixel within image
    if (t < 20) {
        const float* g4 = gt + (size_t)(n * 20 + t) * 4;
        float wmin = floorf(g4[0] * 0.125f);   // x/1024*128, exact
        float hmin = floorf(g4[1] * 0.125f);
        float wmax = ceilf(g4[2] * 0.125f);
        float hmax = ceilf(g4[3] * 0.125f);
        bx[t]      = wmin;
        bx[20 + t] = wmax;
        bx[40 + t] = hmin;
        bx[60 + t] = hmax;
        bx[80 + t] = 1.f / ((hmax + 1.f - hmin) * (wmax + 1.f - wmin));
    }
    wms[t] = w_ms[t];
    wmt[t] = w_mt[t];
    __syncthreads();
    float h = (float)(pix >> 7), w = (float)(pix & 127);
    float mf = 0.f;
#pragma unroll
    for (int b = 0; b < 20; ++b) {
        bool in = (h >= bx[40 + b]) && (h <= bx[60 + b]) &&
                  (w >= bx[b]) && (w <= bx[20 + b]);
        mf = fmaxf(mf, in ? bx[80 + b] : 0.f);
    }
    float bgi = (mf > 0.f) ? 0.f : 1.f;

    const float* Sp = S + (size_t)n * CHW + pix;
    const float* Tp = T + (size_t)n * CHW + pix;
    float fS = 0, fT = 0, cS = 0, cT = 0;
#pragma unroll 8
    for (int c = 0; c < 256; ++c) {
        float sv = __ldg(Sp + (size_t)c * HW);
        float tv = __ldg(Tp + (size_t)c * HW);
        fS += fabsf(sv); fT += fabsf(tv);
        cS += sv * wms[c]; cT += tv * wmt[c];
    }
    // fea/TEMP = (sum/256)/0.5 = sum/128 ; spatial-pool logit: sum (bias drops)
    float eS  = __expf(fS * (1.f / 128.f));
    float eT  = __expf(fT * (1.f / 128.f));
    float ecS = __expf(cS);
    float ecT = __expf(cT);
    int gp = n * HW + pix;
    g_eS[gp] = eS;
    g_eT[gp] = eT;
    g_wpx[gp] = make_float4(eT * mf, eT * bgi, ecS, ecT);

    float v0 = eS, v1 = eT, v2 = ecS, v3 = ecT, v4 = bgi;
    v0 = warpSum(v0); v1 = warpSum(v1); v2 = warpSum(v2);
    v3 = warpSum(v3); v4 = warpSum(v4);
    int lane = t & 31, wid = t >> 5;
    if (lane == 0) {
        rb[0][wid] = v0; rb[1][wid] = v1; rb[2][wid] = v2;
        rb[3][wid] = v3; rb[4][wid] = v4;
    }
    __syncthreads();
    if (t == 0) {
        float z0 = 0, z1 = 0, z2 = 0, z3 = 0, zb = 0;
#pragma unroll
        for (int k = 0; k < 8; ++k) {
            z0 += rb[0][k]; z1 += rb[1][k]; z2 += rb[2][k];
            z3 += rb[3][k]; zb += rb[4][k];
        }
        g_zpart[bid] = make_float4(z0, z1, z2, z3);
        g_bgpart[bid] = zb;
    }
}

// ---------------- pass B: per-(n,c) weighted sums + spatial L1 ----------------
// grid 512 = 8 images x 64 channel-groups of 4; block owns (n, 4 channels, all pixels).
__global__ __launch_bounds__(256) void passB_kernel(
    const float* __restrict__ S, const float* __restrict__ T) {
    int t = threadIdx.x, bid = blockIdx.x;
    int n = bid >> 6;
    int c0 = (bid & 63) * 4;
    int lane = t & 31, wid = t >> 5;
    const float* Sp = S + (size_t)n * CHW + (size_t)c0 * HW;
    const float* Tp = T + (size_t)n * CHW + (size_t)c0 * HW;
    const float4* wp = g_wpx + (size_t)n * HW;

    float a[32];
#pragma unroll
    for (int i = 0; i < 32; ++i) a[i] = 0.f;

#pragma unroll 2
    for (int chunk = 0; chunk < 64; ++chunk) {
        int px = chunk * 256 + t;
        float4 wv = wp[px];
#pragma unroll
        for (int cc = 0; cc < 4; ++cc) {
            float sv = __ldg(Sp + (size_t)cc * HW + px);
            float tv = __ldg(Tp + (size_t)cc * HW + px);
            float d = sv - tv, d2 = d * d;
            a[cc * 8 + 0] += fabsf(sv);
            a[cc * 8 + 1] += fabsf(tv);
            a[cc * 8 + 2] += d2;
            a[cc * 8 + 3] += d;
            a[cc * 8 + 4] += d2 * wv.x;
            a[cc * 8 + 5] += d2 * wv.y;
            a[cc * 8 + 6] += sv * wv.z;
            a[cc * 8 + 7] += tv * wv.w;
        }
    }
#pragma unroll
    for (int i = 0; i < 32; ++i) a[i] = warpSum(a[i]);
    __shared__ float rb[8][32];
    if (lane == 0) {
#pragma unroll
        for (int i = 0; i < 32; ++i) rb[wid][i] = a[i];
    }
    __syncthreads();
    if (t < 32) {
        float s = 0;
#pragma unroll
        for (int w8 = 0; w8 < 8; ++w8) s += rb[w8][t];
        int cc = t >> 3, q = t & 7;
        g_acc[q * 2048 + n * 256 + c0 + cc] = s;   // exclusive owner, no atomic
    }

    if ((bid & 63) == 0) {   // spatial L1 for image n
        __shared__ float zz[2];
        if (t < 32) {
            float4 za = g_zpart[n * 64 + t];
            float4 zb = g_zpart[n * 64 + 32 + t];
            float zs = warpSum(za.x + zb.x);
            float zt = warpSum(za.y + zb.y);
            if (t == 0) { zz[0] = zs; zz[1] = zt; }
        }
        __syncthreads();
        float is = 16384.f / zz[0], it = 16384.f / zz[1];
        const float* eSp = g_eS + (size_t)n * HW;
        const float* eTp = g_eT + (size_t)n * HW;
        float v = 0.f;
#pragma unroll 4
        for (int chunk = 0; chunk < 64; ++chunk) {
            int px = chunk * 256 + t;
            v += fabsf(eSp[px] * is - eTp[px] * it);
        }
        v = warpSum(v);
        __shared__ float r2[8];
        if (lane == 0) r2[wid] = v;
        __syncthreads();
        if (t == 0) {
            float s2 = 0;
#pragma unroll
            for (int k = 0; k < 8; ++k) s2 += r2[k];
            g_spart[n] = s2;
        }
    }
}

// ---------------- epilogue: channel softmax, MLPs, combine ----------------
__device__ void channel_mlp(const float* __restrict__ ctx,   // smem [2048]
                            const float* __restrict__ w1, const float* __restrict__ b1,
                            const float* __restrict__ gam, const float* __restrict__ bet,
                            const float* __restrict__ w2, const float* __restrict__ b2,
                            float* __restrict__ yS,           // smem [1024]
                            float* __restrict__ outp) {       // smem [2048]
    int t = threadIdx.x, w = t >> 5, lane = t & 31;
    const float4* ctx4 = reinterpret_cast<const float4*>(ctx + w * 256);
    float acc[4];
#pragma unroll
    for (int k = 0; k < 4; ++k) acc[k] = b1[lane + 32 * k];
    for (int c4 = 0; c4 < 64; ++c4) {
        float4 cv = ctx4[c4];
#pragma unroll
        for (int k = 0; k < 4; ++k) {
            float4 wv = *reinterpret_cast<const float4*>(w1 + (size_t)(lane + 32 * k) * 256 + c4 * 4);
            acc[k] += cv.x * wv.x + cv.y * wv.y + cv.z * wv.z + cv.w * wv.w;
        }
    }
    float s = 0, s2 = 0;
#pragma unroll
    for (int k = 0; k < 4; ++k) { s += acc[k]; s2 += acc[k] * acc[k]; }
    s = warpSum(s); s2 = warpSum(s2);
    float mean = s * (1.f / 128.f);
    float var = s2 * (1.f / 128.f) - mean * mean;
    float inv = rsqrtf(var + 1e-5f);
#pragma unroll
    for (int k = 0; k < 4; ++k) {
        int j = lane + 32 * k;
        float y = (acc[k] - mean) * inv * gam[j] + bet[j];
        yS[w * 128 + j] = fmaxf(y, 0.f);
    }
    __syncwarp();
    const float4* y4 = reinterpret_cast<const float4*>(yS + w * 128);
    float o[8];
#pragma unroll
    for (int k = 0; k < 8; ++k) o[k] = b2[lane + 32 * k];
    for (int j4 = 0; j4 < 32; ++j4) {
        float4 yv = y4[j4];
#pragma unroll
        for (int k = 0; k < 8; ++k) {
            float4 wv = *reinterpret_cast<const float4*>(w2 + (size_t)(lane + 32 * k) * 128 + j4 * 4);
            o[k] += yv.x * wv.x + yv.y * wv.y + yv.z * wv.z + yv.w * wv.w;
        }
    }
    __syncwarp();
#pragma unroll
    for (int k = 0; k < 8; ++k) outp[w * 256 + lane + 32 * k] = o[k];
    __syncthreads();
}

__global__ __launch_bounds__(256) void final_kernel(
    const float* __restrict__ w1_s, const float* __restrict__ b1_s,
    const float* __restrict__ g_s,  const float* __restrict__ be_s,
    const float* __restrict__ w2_s, const float* __restrict__ b2_s,
    const float* __restrict__ w1_t, const float* __restrict__ b1_t,
    const float* __restrict__ g_t,  const float* __restrict__ be_t,
    const float* __restrict__ w2_t, const float* __restrict__ b2_t,
    float* __restrict__ out) {
    __shared__ __align__(16) float shFS[2048];
    __shared__ __align__(16) float shFT[2048];
    __shared__ __align__(16) float shCS[2048];   // ctx_s, then add_s
    __shared__ __align__(16) float shCT[2048];   // ctx_t, then add_t
    __shared__ __align__(16) float shY[1024];
    __shared__ float shZT[8], shZcS[8], shZcT[8], shBG[8];
    __shared__ float shZ[16];
    __shared__ float shR[8];
    int t = threadIdx.x, w = t >> 5, lane = t & 31;
    {   // per-image reductions of pass-A partials (warp w <-> image w)
        float4 za = g_zpart[w * 64 + lane];
        float4 zb = g_zpart[w * 64 + 32 + lane];
        float zt  = warpSum(za.y + zb.y);
        float zcs = warpSum(za.z + zb.z);
        float zct = warpSum(za.w + zb.w);
        float bg  = warpSum(g_bgpart[w * 64 + lane] + g_bgpart[w * 64 + 32 + lane]);
        if (lane == 0) { shZT[w] = zt; shZcS[w] = zcs; shZcT[w] = zct; shBG[w] = bg; }
    }
    __syncthreads();
#pragma unroll
    for (int n = 0; n < 8; ++n) {
        int i = n * 256 + t;
        // ch/TEMP = (sum/16384)/0.5 = sum/8192
        shFS[i] = __expf(g_acc[i]            * (1.f / 8192.f));
        shFT[i] = __expf(g_acc[2048 + i]     * (1.f / 8192.f));
        shCS[i] = g_acc[6 * 2048 + i] / shZcS[n];
        shCT[i] = g_acc[7 * 2048 + i] / shZcT[n];
    }
    __syncthreads();
    {   // channel-softmax partition functions
        float zS = 0, zT = 0;
#pragma unroll
        for (int k = 0; k < 8; ++k) {
            int c = lane + 32 * k;
            zS += shFS[w * 256 + c];
            zT += shFT[w * 256 + c];
        }
        zS = warpSum(zS); zT = warpSum(zT);
        if (lane == 0) { shZ[w] = zS; shZ[8 + w] = zT; }
    }
    __syncthreads();
    channel_mlp(shCS, w1_s, b1_s, g_s, be_s, w2_s, b2_s, shY, shCS);  // -> add_s
    channel_mlp(shCT, w1_t, b1_t, g_t, be_t, w2_t, b2_t, shY, shCT);  // -> add_t

    float acc = 0.f;
#pragma unroll
    for (int n = 0; n < 8; ++n) {
        int i = n * 256 + t;
        float cS = 256.f * shFS[i] / shZ[n];
        float cT = 256.f * shFT[i] / shZ[8 + n];
        float wn = cT * (16384.f / shZT[n]);
        float bgc = shBG[n];
        float bgw = (bgc > 0.f) ? (1.f / bgc) : 0.f;
        float fg = wn * g_acc[4 * 2048 + i];
        float bg = wn * bgw * g_acc[5 * 2048 + i];
        float mC = fabsf(cS - cT);
        float delta = shCS[i] - shCT[i];
        float rel = g_acc[2 * 2048 + i] + 2.f * delta * g_acc[3 * 2048 + i]
                    + 16384.f * delta * delta;
        acc += 1e-3f * fg + 5e-4f * bg + 1e-3f * mC + 5e-6f * rel;
    }
    acc = warpSum(acc);
    if (lane == 0) shR[w] = acc;
    __syncthreads();
    if (t < 32) {
        float x = (t < 8) ? shR[t] : 0.f;
        x = warpSum(x);
        if (t == 0) {
            float sp = 0;
#pragma unroll
            for (int k = 0; k < 8; ++k) sp += g_spart[k];
            out[0] = (x + 1e-3f * sp) * 0.125f;
        }
    }
}

extern "C" void kernel_launch(void* const* d_in, const int* in_sizes, int n_in,
                              void* d_out, int out_size) {
    const float* S    = (const float*)d_in[0];
    const float* T    = (const float*)d_in[1];
    const float* gt   = (const float*)d_in[2];
    const float* w_ms = (const float*)d_in[3];
    const float* w_mt = (const float*)d_in[5];
    const float* w1_s = (const float*)d_in[7];
    const float* b1_s = (const float*)d_in[8];
    const float* g_s  = (const float*)d_in[9];
    const float* be_s = (const float*)d_in[10];
    const float* w2_s = (const float*)d_in[11];
    const float* b2_s = (const float*)d_in[12];
    const float* w1_t = (const float*)d_in[13];
    const float* b1_t = (const float*)d_in[14];
    const float* g_t  = (const float*)d_in[15];
    const float* be_t = (const float*)d_in[16];
    const float* w2_t = (const float*)d_in[17];
    const float* b2_t = (const float*)d_in[18];

    passA_kernel<<<512, 256>>>(S, T, gt, w_ms, w_mt);
    passB_kernel<<<512, 256>>>(S, T);
    final_kernel<<<1, 256>>>(w1_s, b1_s, g_s, be_s, w2_s, b2_s,
                             w1_t, b1_t, g_t, be_t, w2_t, b2_t,
                             (float*)d_out);
}